// round 16
// baseline (speedup 1.0000x reference)
#include <cuda_runtime.h>
#include <cuda_fp16.h>
#include <cstdint>

// ============================================================================
// Problem constants
// ============================================================================
#define B_DIM 8
#define T_DIM 65536
#define TILE_M 512            // t-rows per tile (16 warps x 32 rows)
#define N_TILES 1024          // (B*T)/TILE_M
#define GRID_MAIN 148         // persistent: 1 CTA per SM
#define XROWS 546             // staged rows: t0-17 .. t0+528
#define XBUF (XROWS * 128)    // 69888
#define WJ_BYTES (64 * 128)   // 8192 per tap (o-major rows of 128B, swizzled)
#define W_BYTES (9 * WJ_BYTES)  // 73728

// smem layout (bytes) for ta_main
#define OFF_BIAS 0
#define OFF_W    256
#define OFF_X0   (OFF_W + W_BYTES)          // 73984
#define OFF_X1   (OFF_X0 + XBUF)            // 143872
#define SMEM_TOTAL (OFF_X1 + XBUF)          // 213760 (1 CTA/SM)

// prep scratch layout: s1[t][c], t-major, pitch 66 words
#define P1 66

// ============================================================================
// Scratch (device globals — no allocation allowed)
// ============================================================================
__device__ __half g_xh[(size_t)B_DIM * T_DIM * 64];  // x as [b][t][c] fp16
__device__ __half g_wh[9 * 64 * 64];                 // w as [j][o][c] fp16

// ============================================================================
// Helpers
// ============================================================================
__device__ __forceinline__ uint32_t smem_to_u32(const void* p) {
    uint32_t a;
    asm("{ .reg .u64 t; cvta.to.shared.u64 t, %1; cvt.u32.u64 %0, t; }" : "=r"(a) : "l"(p));
    return a;
}

__device__ __forceinline__ uint32_t pack_half2(float lo, float hi) {
    __half2 h = __floats2half2_rn(lo, hi);
    return *(const uint32_t*)&h;
}

__device__ __forceinline__ void cp_async16(uint32_t dst, const void* src, int src_bytes) {
    asm volatile("cp.async.cg.shared.global [%0], [%1], 16, %2;"
                 :: "r"(dst), "l"(src), "r"(src_bytes) : "memory");
}
#define CP_COMMIT() asm volatile("cp.async.commit_group;" ::: "memory")
#define CP_WAIT0()  asm volatile("cp.async.wait_group 0;" ::: "memory")

__device__ __forceinline__ void ldsm4(uint32_t& r0, uint32_t& r1, uint32_t& r2, uint32_t& r3,
                                      uint32_t addr) {
    asm volatile("ldmatrix.sync.aligned.m8n8.x4.shared.b16 {%0,%1,%2,%3}, [%4];"
                 : "=r"(r0), "=r"(r1), "=r"(r2), "=r"(r3) : "r"(addr));
}

__device__ __forceinline__ void mma16816(float* c, const uint32_t* a, const uint32_t* b) {
    asm volatile("mma.sync.aligned.m16n8k16.row.col.f32.f16.f16.f32 "
                 "{%0,%1,%2,%3}, {%4,%5,%6,%7}, {%8,%9}, {%0,%1,%2,%3};"
                 : "+f"(c[0]), "+f"(c[1]), "+f"(c[2]), "+f"(c[3])
                 : "r"(a[0]), "r"(a[1]), "r"(a[2]), "r"(a[3]), "r"(b[0]), "r"(b[1]));
}

// ============================================================================
// Prologue 1: weights fp32 [o][c][9] -> fp16 [j][o][c]
// ============================================================================
__global__ void ta_conv_weights(const float* __restrict__ w) {
    int i = blockIdx.x * 256 + threadIdx.x;
    if (i >= 9 * 64 * 64) return;
    int j = i >> 12;
    int rem = i & 4095;
    int o = rem >> 6;
    int c = rem & 63;
    g_wh[j * 4096 + o * 64 + c] = __float2half_rn(w[(o * 64 + c) * 9 + j]);
}

// ============================================================================
// Prologue 2: x fp32 [b][c][t] -> fp16 [b][t][c], smem transpose (proven).
// ============================================================================
__global__ __launch_bounds__(256) void ta_prep(const float* __restrict__ x) {
    __shared__ float s1[128 * P1];        // 33.8 KB
    int tid = threadIdx.x;
    int wid = tid >> 5;
    int lane = tid & 31;
    int b = blockIdx.y;
    int t0 = blockIdx.x * 128;

    // Phase A: coalesced float4 reads along t, scalar transposed STS
    {
        int c = tid >> 2;
        int q0 = tid & 3;
        const float* xrow = x + ((size_t)(b * 64 + c)) * T_DIM + t0;
        #pragma unroll
        for (int q = q0; q < 32; q += 4) {
            float4 v = *(const float4*)(xrow + q * 4);
            int t = q * 4;
            s1[(t + 0) * P1 + c] = v.x;
            s1[(t + 1) * P1 + c] = v.y;
            s1[(t + 2) * P1 + c] = v.z;
            s1[(t + 3) * P1 + c] = v.w;
        }
    }
    __syncthreads();

    // Phase B: one warp per t-row, float2 LDS + coalesced STG
    {
        uint32_t* orow = (uint32_t*)g_xh;
        #pragma unroll
        for (int r = wid; r < 128; r += 8) {
            float2 f = *(const float2*)(s1 + r * P1 + 2 * lane);
            orow[((size_t)b * T_DIM + t0 + r) * 32 + lane] = pack_half2(f.x, f.y);
        }
    }
}

// ============================================================================
// X tile stage: fp16 [b][t][c] rows -> swizzled smem buffer via cp.async
// ============================================================================
__device__ __forceinline__ void stage_x(uint32_t xdst, int b, int t0, int tid) {
    for (int i = tid; i < XROWS * 8; i += 512) {
        int s = i >> 3, ch = i & 7;
        int t = t0 - 17 + s;
        const char* src = (const char*)(g_xh + ((size_t)b * T_DIM + t) * 64) + ch * 16;
        uint32_t dst = xdst + s * 128 + ((ch ^ (s & 7)) * 16);
        cp_async16(dst, src, ((unsigned)t < (unsigned)T_DIM) ? 16 : 0);
    }
}

// ============================================================================
// Main kernel (persistent): grid=148, 512 threads (16 warps, 32x64 tiles).
//   W staged ONCE per CTA. X double-buffered: prefetch tile i+148 via
//   cp.async while computing tile i. Inner loop = proven round-15 scheme.
// ============================================================================
__global__ __launch_bounds__(512, 1) void ta_main(const float* __restrict__ bias,
                                                  float* __restrict__ out) {
    extern __shared__ char smem[];
    uint32_t sb = smem_to_u32(smem);
    int tid = threadIdx.x;
    int wid = tid >> 5;
    int lane = tid & 31;

    if (tid < 64) ((float*)(smem + OFF_BIAS))[tid] = bias[tid];

    // ---- stage weights (once) + first X tile ----
    {
        const char* wsrc = (const char*)g_wh;
        for (int i = tid; i < 576 * 8; i += 512) {
            int row = i >> 3, ch = i & 7;
            uint32_t dst = sb + OFF_W + row * 128 + ((ch ^ (row & 7)) * 16);
            cp_async16(dst, wsrc + row * 128 + ch * 16, 16);
        }
        int tile = blockIdx.x;
        stage_x(sb + OFF_X0, tile >> 7, (tile & 127) * TILE_M, tid);
        CP_COMMIT();
    }

    // lane-dependent ldmatrix address components
    const int a_lrow = lane & 15;
    const int a_lcol = (lane >> 4) << 3;                 // 0 or 8 (halves)
    const int b_lrow = ((lane & 16) >> 1) + (lane & 7);  // 0..15
    const int b_lcol = lane & 8;                         // 0 or 8 (halves)
    const int b_sw = b_lrow & 7;

    const uint32_t wbase = sb + OFF_W;
    const float* sbias = (const float*)(smem + OFF_BIAS);
    int cur = 0;

    for (int tile = blockIdx.x; tile < N_TILES; tile += GRID_MAIN) {
        const int b = tile >> 7;
        const int t0 = (tile & 127) * TILE_M;

        CP_WAIT0();
        __syncthreads();          // current buffer (and W on iter 0) visible

        // prefetch next tile into the other buffer
        int ntile = tile + GRID_MAIN;
        if (ntile < N_TILES) {
            stage_x(sb + (cur ? OFF_X0 : OFF_X1), ntile >> 7, (ntile & 127) * TILE_M, tid);
            CP_COMMIT();
        }

        const uint32_t xbase = sb + (cur ? OFF_X1 : OFF_X0);

        float acc[2][8][4];
        #pragma unroll
        for (int mi = 0; mi < 2; mi++)
            #pragma unroll
            for (int ni = 0; ni < 8; ni++)
                #pragma unroll
                for (int r = 0; r < 4; r++) acc[mi][ni][r] = 0.0f;

        const int tb = 17 + wid * 32 + a_lrow;

        #pragma unroll
        for (int kk = 0; kk < 4; kk++) {
            const int c0 = kk * 16;
            const uint32_t bchunk = (uint32_t)((((c0 + b_lcol) >> 3) ^ b_sw) * 16);
            #pragma unroll
            for (int d = -1; d <= 1; d++) {
                const int rowbase = tb + d - 16;
                const int a_sw = rowbase & 7;
                const uint32_t achunk = (uint32_t)((((c0 + a_lcol) >> 3) ^ a_sw) * 16);
                uint32_t af[4][4];
                #pragma unroll
                for (int i = 0; i < 4; i++)
                    ldsm4(af[i][0], af[i][1], af[i][2], af[i][3],
                          xbase + (uint32_t)(rowbase + i * 16) * 128 + achunk);
                #pragma unroll
                for (int g = 0; g < 3; g++) {
                    const int j = 3 * g + (d + 1);
                    const uint32_t wj = wbase + j * WJ_BYTES;
                    uint32_t bb[4][4];
                    #pragma unroll
                    for (int bi = 0; bi < 4; bi++)
                        ldsm4(bb[bi][0], bb[bi][1], bb[bi][2], bb[bi][3],
                              wj + (uint32_t)(bi * 16 + b_lrow) * 128 + bchunk);
                    #pragma unroll
                    for (int mi = 0; mi < 2; mi++)
                        #pragma unroll
                        for (int bi = 0; bi < 4; bi++) {
                            mma16816(acc[mi][2 * bi], af[g + mi], bb[bi] + 0);
                            mma16816(acc[mi][2 * bi + 1], af[g + mi], bb[bi] + 2);
                        }
                }
            }
        }

        // ---- epilogue: D fragment (row=t, col=o), add bias, store ----
        {
            int trow = t0 + wid * 32 + (lane >> 2);
            int ocol = 2 * (lane & 3);
            #pragma unroll
            for (int mi = 0; mi < 2; mi++) {
                #pragma unroll
                for (int ni = 0; ni < 8; ni++) {
                    int t = trow + mi * 16;
                    int o = ocol + ni * 8;
                    size_t base = ((size_t)b * 64 + o) * T_DIM + t;
                    float bz0 = sbias[o], bz1 = sbias[o + 1];
                    out[base] = acc[mi][ni][0] + bz0;
                    out[base + T_DIM] = acc[mi][ni][1] + bz1;
                    out[base + 8] = acc[mi][ni][2] + bz0;
                    out[base + T_DIM + 8] = acc[mi][ni][3] + bz1;
                }
            }
        }
        cur ^= 1;
    }
}

// ============================================================================
// Launch
// ============================================================================
extern "C" void kernel_launch(void* const* d_in, const int* in_sizes, int n_in,
                              void* d_out, int out_size) {
    const float* x = (const float*)d_in[0];
    const float* w = (const float*)d_in[1];
    const float* bias = (const float*)d_in[2];
    float* out = (float*)d_out;

    cudaFuncSetAttribute(ta_main, cudaFuncAttributeMaxDynamicSharedMemorySize, SMEM_TOTAL);

    ta_conv_weights<<<(9 * 64 * 64 + 255) / 256, 256>>>(w);
    ta_prep<<<dim3(T_DIM / 128, B_DIM), 256>>>(x);
    ta_main<<<GRID_MAIN, 512, SMEM_TOTAL>>>(bias, out);
}